// round 1
// baseline (speedup 1.0000x reference)
#include <cuda_runtime.h>

// XY model log-density: out[s] = sum_i cos(x[up(i)] - x[i]) + cos(x[right(i)] - x[i])
// Lattice 64x64 (4096 sites), 16384 samples. BETA = 1.
//
// Strategy: one CTA per sample. Stage the 16KB row in shared memory
// (float4 coalesced), compute neighbor indices arithmetically (identical to
// the reference shift table), 2x MUFU.COS per site via __cosf, block reduce.

#define LATTICE 4096
#define THREADS 256
#define SITES_PER_THREAD (LATTICE / THREADS)  // 16

__global__ __launch_bounds__(THREADS) void xy_hamiltonian_kernel(
    const float* __restrict__ state,
    float* __restrict__ out)
{
    __shared__ float sm[LATTICE];
    __shared__ float warp_sums[THREADS / 32];

    const int row = blockIdx.x;
    const float4* __restrict__ rp4 =
        reinterpret_cast<const float4*>(state + (size_t)row * LATTICE);
    float4* sm4 = reinterpret_cast<float4*>(sm);

    // Cooperative vectorized load of the row: 1024 float4 = 16KB
    #pragma unroll
    for (int k = 0; k < LATTICE / 4 / THREADS; k++) {
        int i = threadIdx.x + k * THREADS;
        sm4[i] = rp4[i];
    }
    __syncthreads();

    float acc = 0.0f;
    #pragma unroll
    for (int k = 0; k < SITES_PER_THREAD; k++) {
        int i = threadIdx.x + k * THREADS;
        float x  = sm[i];
        float xu = sm[(i + 64) & (LATTICE - 1)];            // up neighbor (row+1 mod 64)
        float xr = sm[(i & ~63) | ((i + 1) & 63)];          // right neighbor (col+1 mod 64)
        acc += __cosf(xu - x);
        acc += __cosf(xr - x);
    }

    // Warp reduce
    #pragma unroll
    for (int o = 16; o > 0; o >>= 1)
        acc += __shfl_down_sync(0xffffffffu, acc, o);
    if ((threadIdx.x & 31) == 0)
        warp_sums[threadIdx.x >> 5] = acc;
    __syncthreads();

    // Final reduce across 8 warps (done by first 8 lanes of warp 0)
    if (threadIdx.x < 8) {
        float v = warp_sums[threadIdx.x];
        #pragma unroll
        for (int o = 4; o > 0; o >>= 1)
            v += __shfl_down_sync(0x000000ffu, v, o);
        if (threadIdx.x == 0)
            out[row] = v;
    }
}

extern "C" void kernel_launch(void* const* d_in, const int* in_sizes, int n_in,
                              void* d_out, int out_size)
{
    const float* state = (const float*)d_in[0];
    // d_in[1] is the shift table (int64) — indices are computed arithmetically
    // in-kernel (identical mapping), so it is unused.
    float* out = (float*)d_out;

    const int n_samples = in_sizes[0] / LATTICE;  // 16384
    xy_hamiltonian_kernel<<<n_samples, THREADS>>>(state, out);
}